// round 2
// baseline (speedup 1.0000x reference)
#include <cuda_runtime.h>
#include <math.h>

#define NN 50000
#define EE 800000
#define TT 12
#define D  128
#define G4 (4*D)   // 512 gates

// ---------------- scratch (device globals: no allocation allowed) ----------------
__device__ float g_norm_src[NN];
__device__ float g_norm_dst[NN];
__device__ int   g_ocnt[NN];
__device__ int   g_cnt[NN + 1];
__device__ int   g_rowptr[NN + 1];
__device__ int   g_cursor[NN];
__device__ int   g_srcsorted[EE];
__device__ float g_x[(size_t)NN * D];       // layer activations
__device__ float g_m[(size_t)NN * D];       // spmm output
__device__ float g_hstate[(size_t)NN * D];  // LSTM h
__device__ float g_cstate[(size_t)NN * D];  // LSTM c
__device__ float g_gates[(size_t)NN * G4];  // LSTM gates buffer
__device__ float g_hs[TT * D];              // hs accumulators
__device__ float g_bias[G4];                // b_ih + b_hh

// ---------------- helpers ----------------
__device__ __forceinline__ float gelu_exact(float v) {
    return 0.5f * v * (1.0f + erff(v * 0.70710678118654752f));
}
__device__ __forceinline__ float sigmoidf(float v) {
    return 1.0f / (1.0f + __expf(-v));
}

// ---------------- init ----------------
__global__ void init_kernel(float* __restrict__ out_ht) {
    int i = blockIdx.x * blockDim.x + threadIdx.x;
    if (i < NN * D) {
        g_hstate[i] = 0.0f;
        g_cstate[i] = 0.0f;
        out_ht[i]   = 0.0f;
    }
    if (i < NN) { g_ocnt[i] = 0; g_cnt[i] = 0; }
    if (i == 0) g_cnt[NN] = 0;
    if (i < TT * D) g_hs[i] = 0.0f;
}

__global__ void hist_kernel(const int* __restrict__ src, const int* __restrict__ dst) {
    int e = blockIdx.x * blockDim.x + threadIdx.x;
    if (e < EE) {
        atomicAdd(&g_ocnt[src[e]], 1);
        atomicAdd(&g_cnt[dst[e]], 1);
    }
}

__global__ void norm_kernel() {
    int i = blockIdx.x * blockDim.x + threadIdx.x;
    if (i < NN) {
        g_norm_src[i] = rsqrtf(fmaxf((float)g_ocnt[i], 1.0f));
        g_norm_dst[i] = rsqrtf(fmaxf((float)g_cnt[i], 1.0f));
    }
}

__global__ void bias_kernel(const float* __restrict__ b_ih, const float* __restrict__ b_hh) {
    int i = blockIdx.x * blockDim.x + threadIdx.x;
    if (i < G4) g_bias[i] = b_ih[i] + b_hh[i];
}

// single-block exclusive scan of g_cnt[0..NN) -> g_rowptr, init cursor
__global__ void scan_kernel() {
    __shared__ int ps[1024];
    const int CH = (NN + 1023) / 1024;  // 49
    int t = threadIdx.x;
    int beg = t * CH;
    int end = min(beg + CH, NN);
    int s = 0;
    for (int i = beg; i < end; i++) s += g_cnt[i];
    ps[t] = s;
    __syncthreads();
    if (t == 0) {
        int a = 0;
        for (int i = 0; i < 1024; i++) { int v = ps[i]; ps[i] = a; a += v; }
    }
    __syncthreads();
    int off = ps[t];
    for (int i = beg; i < end; i++) {
        g_rowptr[i] = off;
        g_cursor[i] = off;
        off += g_cnt[i];
    }
    if (t == 1023) g_rowptr[NN] = off;  // = EE
}

__global__ void scatter_kernel(const int* __restrict__ src, const int* __restrict__ dst) {
    int e = blockIdx.x * blockDim.x + threadIdx.x;
    if (e < EE) {
        int d = dst[e];
        int p = atomicAdd(&g_cursor[d], 1);
        g_srcsorted[p] = src[e];
    }
}

// ---------------- SpMM: m[d] = norm_dst[d] * sum_{e: dst=d} norm_src[src] * X[src]
// one warp per dst row, float4 per lane (128 dims = 32 lanes * 4)
__global__ __launch_bounds__(256) void spmm_kernel(const float* __restrict__ X, int ldx,
                                                   float* __restrict__ M) {
    int w = (blockIdx.x * blockDim.x + threadIdx.x) >> 5;
    int lane = threadIdx.x & 31;
    if (w >= NN) return;
    int s0 = g_rowptr[w];
    int s1 = g_rowptr[w + 1];
    float4 acc = make_float4(0.f, 0.f, 0.f, 0.f);
    for (int base = s0; base < s1; base += 32) {
        int n = min(32, s1 - base);
        int s = 0; float ns = 0.f;
        if (lane < n) {
            s = g_srcsorted[base + lane];
            ns = g_norm_src[s];
        }
        for (int j = 0; j < n; j++) {
            int   sj = __shfl_sync(0xffffffffu, s, j);
            float nj = __shfl_sync(0xffffffffu, ns, j);
            float4 v = *(const float4*)(X + (size_t)sj * ldx + lane * 4);
            acc.x += v.x * nj; acc.y += v.y * nj;
            acc.z += v.z * nj; acc.w += v.w * nj;
        }
    }
    float nd = g_norm_dst[w];
    float4 o = make_float4(acc.x * nd, acc.y * nd, acc.z * nd, acc.w * nd);
    *(float4*)(M + (size_t)w * D + lane * 4) = o;
}

// ---------------- GEMM: C[M x ncols] = gelu(A[M x K] @ B[K x ncols] + bias)
// BM=128 BN=64 BK=8, 256 threads, 8x4 microtile. Optional column-sum into g_hs[t].
__global__ __launch_bounds__(256) void gemm_gelu_kernel(
    const float* __restrict__ A, int lda,
    const float* __restrict__ B, int ncols,
    const float* __restrict__ bias,
    float* __restrict__ C,
    int M, int K, int colsum_t) {
    __shared__ float As[8][128];
    __shared__ float Bs[8][64];
    __shared__ float Cs[16][68];

    int tid = threadIdx.x;
    int tx = tid & 15, ty = tid >> 4;
    int rowBase = blockIdx.x * 128;
    int colBase = blockIdx.y * 64;

    float acc[8][4];
#pragma unroll
    for (int i = 0; i < 8; i++)
#pragma unroll
        for (int j = 0; j < 4; j++) acc[i][j] = 0.f;

    for (int k0 = 0; k0 < K; k0 += 8) {
        {
            int r = tid >> 1, kq = (tid & 1) * 4;
            float4 v = make_float4(0.f, 0.f, 0.f, 0.f);
            if (rowBase + r < M)
                v = *(const float4*)(A + (size_t)(rowBase + r) * lda + k0 + kq);
            As[kq + 0][r] = v.x; As[kq + 1][r] = v.y;
            As[kq + 2][r] = v.z; As[kq + 3][r] = v.w;
        }
        {
            int kk = tid >> 5, j = (tid & 31) * 2;
            float2 v = *(const float2*)(B + (size_t)(k0 + kk) * ncols + colBase + j);
            Bs[kk][j] = v.x; Bs[kk][j + 1] = v.y;
        }
        __syncthreads();
#pragma unroll
        for (int kk = 0; kk < 8; kk++) {
            float4 a0 = *(const float4*)(&As[kk][ty * 8]);
            float4 a1 = *(const float4*)(&As[kk][ty * 8 + 4]);
            float4 bv = *(const float4*)(&Bs[kk][tx * 4]);
            float a[8] = {a0.x, a0.y, a0.z, a0.w, a1.x, a1.y, a1.z, a1.w};
            float b[4] = {bv.x, bv.y, bv.z, bv.w};
#pragma unroll
            for (int i = 0; i < 8; i++)
#pragma unroll
                for (int j = 0; j < 4; j++) acc[i][j] += a[i] * b[j];
        }
        __syncthreads();
    }

    float csum[4] = {0.f, 0.f, 0.f, 0.f};
#pragma unroll
    for (int i = 0; i < 8; i++) {
        int r = rowBase + ty * 8 + i;
        if (r < M) {
            float4 o;
            float* po = &o.x;
#pragma unroll
            for (int j = 0; j < 4; j++) {
                float v = acc[i][j] + bias[colBase + tx * 4 + j];
                v = gelu_exact(v);
                po[j] = v;
                csum[j] += v;
            }
            *(float4*)(C + (size_t)r * ncols + colBase + tx * 4) = o;
        }
    }
    if (colsum_t >= 0) {
#pragma unroll
        for (int j = 0; j < 4; j++) Cs[ty][tx * 4 + j] = csum[j];
        __syncthreads();
        for (int s = 8; s > 0; s >>= 1) {
            if (ty < s) {
#pragma unroll
                for (int j = 0; j < 4; j++)
                    Cs[ty][tx * 4 + j] += Cs[ty + s][tx * 4 + j];
            }
            __syncthreads();
        }
        if (ty == 0) {
#pragma unroll
            for (int j = 0; j < 4; j++)
                atomicAdd(&g_hs[colsum_t * D + colBase + tx * 4 + j], Cs[0][tx * 4 + j]);
        }
    }
}

// ---------------- LSTM gates GEMM: g_gates = Xt@Wih^T + h@Whh^T + (b_ih+b_hh)
// Xt strided (ld = TT*D). Wih/Whh are (512 x 128) row-major (B^T form).
__global__ __launch_bounds__(256) void lstm_gates_kernel(
    const float* __restrict__ Xt,
    const float* __restrict__ Wih, const float* __restrict__ Whh) {
    __shared__ float As[8][128];
    __shared__ float Bs[8][64];

    int tid = threadIdx.x;
    int tx = tid & 15, ty = tid >> 4;
    int rowBase = blockIdx.x * 128;
    int colBase = blockIdx.y * 64;

    float acc[8][4];
#pragma unroll
    for (int i = 0; i < 8; i++)
#pragma unroll
        for (int j = 0; j < 4; j++) acc[i][j] = 0.f;

    for (int k0 = 0; k0 < 2 * D; k0 += 8) {
        const float* Ap;
        const float* Bp;
        int lda_, kk0;
        if (k0 < D) { Ap = Xt;        lda_ = TT * D; kk0 = k0;     Bp = Wih; }
        else        { Ap = g_hstate;  lda_ = D;      kk0 = k0 - D; Bp = Whh; }
        {
            int r = tid >> 1, kq = (tid & 1) * 4;
            float4 v = make_float4(0.f, 0.f, 0.f, 0.f);
            if (rowBase + r < NN)
                v = *(const float4*)(Ap + (size_t)(rowBase + r) * lda_ + kk0 + kq);
            As[kq + 0][r] = v.x; As[kq + 1][r] = v.y;
            As[kq + 2][r] = v.z; As[kq + 3][r] = v.w;
        }
        if (tid < 128) {
            int j = tid >> 1, kq = (tid & 1) * 4;
            float4 v = *(const float4*)(Bp + (size_t)(colBase + j) * D + kk0 + kq);
            Bs[kq + 0][j] = v.x; Bs[kq + 1][j] = v.y;
            Bs[kq + 2][j] = v.z; Bs[kq + 3][j] = v.w;
        }
        __syncthreads();
#pragma unroll
        for (int kk = 0; kk < 8; kk++) {
            float4 a0 = *(const float4*)(&As[kk][ty * 8]);
            float4 a1 = *(const float4*)(&As[kk][ty * 8 + 4]);
            float4 bv = *(const float4*)(&Bs[kk][tx * 4]);
            float a[8] = {a0.x, a0.y, a0.z, a0.w, a1.x, a1.y, a1.z, a1.w};
            float b[4] = {bv.x, bv.y, bv.z, bv.w};
#pragma unroll
            for (int i = 0; i < 8; i++)
#pragma unroll
                for (int j = 0; j < 4; j++) acc[i][j] += a[i] * b[j];
        }
        __syncthreads();
    }

#pragma unroll
    for (int i = 0; i < 8; i++) {
        int r = rowBase + ty * 8 + i;
        if (r < NN) {
            float4 o;
            float* po = &o.x;
#pragma unroll
            for (int j = 0; j < 4; j++)
                po[j] = acc[i][j] + g_bias[colBase + tx * 4 + j];
            *(float4*)(g_gates + (size_t)r * G4 + colBase + tx * 4) = o;
        }
    }
}

__global__ void lstm_elem_kernel(float* __restrict__ out_ht) {
    int idx = blockIdx.x * blockDim.x + threadIdx.x;
    if (idx >= NN * D) return;
    int n = idx >> 7;
    int j = idx & 127;
    const float* gr = g_gates + (size_t)n * G4;
    float i_ = gr[j];
    float f_ = gr[D + j];
    float gg = gr[2 * D + j];
    float o_ = gr[3 * D + j];
    float cp = g_cstate[idx];
    float c  = sigmoidf(f_) * cp + sigmoidf(i_) * tanhf(gg);
    float ho = sigmoidf(o_) * tanhf(c);
    g_cstate[idx] = c;
    g_hstate[idx] = ho;
    out_ht[idx] += ho;
}

__global__ void finalize_kernel(float* __restrict__ out) {
    int idx = blockIdx.x * blockDim.x + threadIdx.x;
    if (idx < TT * D) out[idx] = g_hs[idx] * (1.0f / (float)NN);
    if (idx < NN * D) out[TT * D + idx] *= (1.0f / (float)TT);
}

// ---------------- launch ----------------
extern "C" void kernel_launch(void* const* d_in, const int* in_sizes, int n_in,
                              void* d_out, int out_size) {
    const float* h    = (const float*)d_in[0];
    const int*   src  = (const int*)d_in[1];
    const int*   dst  = (const int*)d_in[2];
    const float* Wg1  = (const float*)d_in[3];
    const float* bg1  = (const float*)d_in[4];
    const float* Wg2  = (const float*)d_in[5];
    const float* bg2  = (const float*)d_in[6];
    const float* w_ih = (const float*)d_in[7];
    const float* w_hh = (const float*)d_in[8];
    const float* b_ih = (const float*)d_in[9];
    const float* b_hh = (const float*)d_in[10];

    float* out    = (float*)d_out;
    float* out_ht = out + TT * D;

    float *pm, *px;
    cudaGetSymbolAddress((void**)&pm, g_m);
    cudaGetSymbolAddress((void**)&px, g_x);

    init_kernel<<<(NN * D + 255) / 256, 256>>>(out_ht);
    hist_kernel<<<(EE + 255) / 256, 256>>>(src, dst);
    norm_kernel<<<(NN + 255) / 256, 256>>>();
    bias_kernel<<<2, 256>>>(b_ih, b_hh);
    scan_kernel<<<1, 1024>>>();
    scatter_kernel<<<(EE + 255) / 256, 256>>>(src, dst);

    dim3 ggrid((NN + 127) / 128, D / 64);       // 391 x 2
    dim3 lgrid((NN + 127) / 128, G4 / 64);      // 391 x 8
    int spmm_blocks = (NN * 32 + 255) / 256;

    // graph conv tower (independent of LSTM)
    for (int t = 0; t < TT; t++) {
        spmm_kernel<<<spmm_blocks, 256>>>(h + t * D, TT * D, pm);
        gemm_gelu_kernel<<<ggrid, 256>>>(pm, D, Wg1, D, bg1, px, NN, D, -1);
        spmm_kernel<<<spmm_blocks, 256>>>(px, D, pm);
        gemm_gelu_kernel<<<ggrid, 256>>>(pm, D, Wg2, D, bg2, px, NN, D, t);
    }

    // LSTM over T steps
    for (int t = 0; t < TT; t++) {
        lstm_gates_kernel<<<lgrid, 256>>>(h + t * D, w_ih, w_hh);
        lstm_elem_kernel<<<(NN * D + 255) / 256, 256>>>(out_ht);
    }

    finalize_kernel<<<(NN * D + 255) / 256, 256>>>(out);
}